// round 15
// baseline (speedup 1.0000x reference)
#include <cuda_runtime.h>
#include <cuda_bf16.h>
#include <math.h>
#include <stdint.h>

#define N_NODES 10000
#define N_EDGES 160000
#define FDIM    256
#define HCW     768   // hcat: [h(256) | temb(256) | emb_pcs(256)]
#define ABW     512   // [A(256) | B(256)] per node

// node gemm tiling: 64(M) x 128(N), KC=64, 8 warps (2m x 4n)
#define BM   64
#define BN   128
#define KC   64
#define A_TILE (BM * KC * 2)
#define B_TILE (BN * KC * 2)
#define STAGE  (2 * A_TILE + 2 * B_TILE)       // 49152 B
#define DSMEM  (2 * STAGE + 128)               // ~96KB -> 2 CTA/SM

// edge gemm: 64 edges x FULL N=256, KC=32, 512 threads, 1 CTA/SM
#define EKC       32
#define EA2_TILE  (64 * EKC * 2)               // 4096 B (hi)
#define EB2_TILE  (256 * EKC * 2)              // 16384 B (hi)
#define ESTAGE2   (2 * EA2_TILE + 2 * EB2_TILE)  // 40960 B
#define DSMEM_EDGE (2 * ESTAGE2 + 128)         // ~80KB (also holds 64KB C stash)

// -------- device scratch ----------------------------------------------------
__device__ __align__(16) float g_AB  [N_NODES * ABW];
__device__ __align__(16) float g_seg [N_NODES * FDIM];
__device__ __align__(16) __nv_bfloat16 g_hHi[(N_NODES + 64) * HCW];
__device__ __align__(16) __nv_bfloat16 g_hLo[(N_NODES + 64) * HCW];
__device__ __align__(16) __nv_bfloat16 g_Bhi[512 * 768];   // W^T hi [n][k]
__device__ __align__(16) __nv_bfloat16 g_Blo[512 * 768];   // W^T lo [n][k]
// edge sort
__device__ int g_cnt[N_NODES];
__device__ int g_cur[N_NODES];
__device__ int g_srt_src[N_EDGES];
__device__ int g_srt_dst[N_EDGES];

// -------- helpers -----------------------------------------------------------
__device__ __forceinline__ void atomicMaxF(float* addr, float v) {
    if (v >= 0.0f) atomicMax((int*)addr, __float_as_int(v));
    else           atomicMin((unsigned int*)addr, __float_as_uint(v));
}
__device__ __forceinline__ uint32_t smem_u32(const void* p) {
    uint32_t a;
    asm("{ .reg .u64 t; cvta.to.shared.u64 t, %1; cvt.u32.u64 %0, t; }" : "=r"(a) : "l"(p));
    return a;
}
__device__ __forceinline__ void ldsm4(uint32_t* r, uint32_t addr) {
    asm volatile("ldmatrix.sync.aligned.m8n8.x4.shared.b16 {%0,%1,%2,%3}, [%4];"
                 : "=r"(r[0]), "=r"(r[1]), "=r"(r[2]), "=r"(r[3]) : "r"(addr));
}
__device__ __forceinline__ void mma16816(float* c, const uint32_t* a,
                                         uint32_t b0, uint32_t b1) {
    asm volatile("mma.sync.aligned.m16n8k16.row.col.f32.bf16.bf16.f32 "
                 "{%0,%1,%2,%3}, {%4,%5,%6,%7}, {%8,%9}, {%0,%1,%2,%3};"
                 : "+f"(c[0]), "+f"(c[1]), "+f"(c[2]), "+f"(c[3])
                 : "r"(a[0]), "r"(a[1]), "r"(a[2]), "r"(a[3]), "r"(b0), "r"(b1));
}
__device__ __forceinline__ void cp16(uint32_t daddr, const void* gptr) {
    asm volatile("cp.async.cg.shared.global [%0], [%1], 16;"
                 :: "r"(daddr), "l"(gptr) : "memory");
}
#define CP_COMMIT() asm volatile("cp.async.commit_group;" ::: "memory")
#define CP_WAIT0()  asm volatile("cp.async.wait_group 0;" ::: "memory")

__device__ __forceinline__ void split2(float z0, float z1, uint32_t& hi, uint32_t& lo) {
    __nv_bfloat16 h0 = __float2bfloat16(z0), h1 = __float2bfloat16(z1);
    __nv_bfloat16 l0 = __float2bfloat16(z0 - __bfloat162float(h0));
    __nv_bfloat16 l1 = __float2bfloat16(z1 - __bfloat162float(h1));
    hi = (uint32_t)__bfloat16_as_ushort(h0) | ((uint32_t)__bfloat16_as_ushort(h1) << 16);
    lo = (uint32_t)__bfloat16_as_ushort(l0) | ((uint32_t)__bfloat16_as_ushort(l1) << 16);
}
__device__ __forceinline__ void split1(float v, __nv_bfloat16& hi, __nv_bfloat16& lo) {
    hi = __float2bfloat16(v);
    lo = __float2bfloat16(v - __bfloat162float(hi));
}

// ============================================================================
// edge sort: counting sort by dst (order within dst nondeterministic — OK,
// max is order-independent, exact in fp32)
// ============================================================================
__global__ void zero_cnt_kernel() {
    int i = blockIdx.x * 256 + threadIdx.x;
    if (i < N_NODES) g_cnt[i] = 0;
}
__global__ void hist_kernel(const int* __restrict__ eidx) {
    int e = blockIdx.x * 256 + threadIdx.x;
    atomicAdd(&g_cnt[eidx[N_EDGES + e]], 1);
}
__global__ void scan_kernel() {     // 1 block, 1024 threads, 10 elems/thread
    __shared__ int sTot[1024];
    int tx = threadIdx.x;
    int base = tx * 10;
    int local[10];
    int s = 0;
    if (tx < 1000) {
#pragma unroll
        for (int j = 0; j < 10; j++) { local[j] = s; s += g_cnt[base + j]; }
    }
    sTot[tx] = (tx < 1000) ? s : 0;
    __syncthreads();
    for (int off = 1; off < 1024; off <<= 1) {
        int add = (tx >= off) ? sTot[tx - off] : 0;
        __syncthreads();
        sTot[tx] += add;
        __syncthreads();
    }
    if (tx < 1000) {
        int pre = (tx == 0) ? 0 : sTot[tx - 1];
#pragma unroll
        for (int j = 0; j < 10; j++) g_cur[base + j] = pre + local[j];
    }
}
__global__ void scatter_kernel(const int* __restrict__ eidx) {
    int e = blockIdx.x * 256 + threadIdx.x;
    int d = eidx[N_EDGES + e];
    int pos = atomicAdd(&g_cur[d], 1);
    g_srt_dst[pos] = d;
    g_srt_src[pos] = eidx[e];
}

// ============================================================================
// small kernels — temb/enc/fin12 write PRE-SPLIT bf16 hi/lo hcat
// ============================================================================
__global__ void temb_kernel(const float* __restrict__ t, const float* __restrict__ fw,
                            const float* __restrict__ teW, const float* __restrict__ teb) {
    __shared__ float v[8][256];
    int j = threadIdx.x, i0 = blockIdx.x * 8;
    if (j < 128) {
        float f = fw[j] * 6.283185307179586f;
#pragma unroll
        for (int r = 0; r < 8; r++) {
            float p = t[i0 + r] * f;
            v[r][j] = sinf(p); v[r][j + 128] = cosf(p);
        }
    }
    __syncthreads();
    float acc[8]; float bb = teb[j];
#pragma unroll
    for (int r = 0; r < 8; r++) acc[r] = bb;
    for (int k = 0; k < 256; k++) {
        float w = teW[k * 256 + j];
#pragma unroll
        for (int r = 0; r < 8; r++) acc[r] = fmaf(v[r][k], w, acc[r]);
    }
#pragma unroll
    for (int r = 0; r < 8; r++) {
        float a = acc[r];
        a = a / (1.0f + expf(-a));
        __nv_bfloat16 hi, lo; split1(a, hi, lo);
        size_t off = (size_t)(i0 + r) * HCW + 256 + j;
        g_hHi[off] = hi; g_hLo[off] = lo;
    }
}

__global__ void enc_kernel(const float* __restrict__ x, const float* __restrict__ encW,
                           const float* __restrict__ encb, const float* __restrict__ emb) {
    int i = blockIdx.x, j = threadIdx.x;
    float h = encb[j];
    h = fmaf(x[i * 3 + 0], encW[0 * 256 + j], h);
    h = fmaf(x[i * 3 + 1], encW[1 * 256 + j], h);
    h = fmaf(x[i * 3 + 2], encW[2 * 256 + j], h);
    __nv_bfloat16 hi, lo;
    split1(h, hi, lo);
    g_hHi[(size_t)i * HCW + j] = hi; g_hLo[(size_t)i * HCW + j] = lo;
    split1(emb[(size_t)i * 256 + j], hi, lo);
    g_hHi[(size_t)i * HCW + 512 + j] = hi; g_hLo[(size_t)i * HCW + 512 + j] = lo;
}

__global__ void prepWc_kernel(const float* __restrict__ W1) {
    int idx = blockIdx.x * 256 + threadIdx.x;     // 512*768
    int n = idx / 768, k = idx % 768;
    float v = (n < 256) ? (W1[k * 256 + n] - W1[(768 + k) * 256 + n])
                        : W1[(768 + k) * 256 + (n - 256)];
    __nv_bfloat16 hi, lo; split1(v, hi, lo);
    g_Bhi[idx] = hi; g_Blo[idx] = lo;
}

__global__ void prepW2_kernel(const float* __restrict__ W2) {
    int idx = blockIdx.x * 256 + threadIdx.x;     // 256*256
    int n = idx / 256, k = idx % 256;
    __nv_bfloat16 hi, lo; split1(W2[k * 256 + n], hi, lo);
    g_Bhi[idx] = hi; g_Blo[idx] = lo;
}

__global__ void init_kernel(int n) {
    int idx = blockIdx.x * 256 + threadIdx.x;
    if (idx < n) g_seg[idx] = __int_as_float(0xff800000);
}

// ============================================================================
// node gemm: g_AB[M,512] = hcat[M,768] @ Wc^T — all operands via cp.async
// (R10 version, measured 77us)
// ============================================================================
__global__ __launch_bounds__(256, 2)
void node_gemm(int M) {
    extern __shared__ __align__(128) char dsm[];
    char* sbase = (char*)(((uintptr_t)dsm + 127) & ~(uintptr_t)127);
    const uint32_t usm = smem_u32(sbase);

    const int tid  = threadIdx.x;
    const int wid  = tid >> 5, lane = tid & 31;
    const int wm   = wid & 1;
    const int wn   = wid >> 1;
    const int m0   = blockIdx.x * BM;
    const int n0   = blockIdx.y * BN;
    const int nChunks = HCW / KC;   // 12

    const int ar = tid >> 2, ajj = (tid & 3) * 2;
    auto cpA = [&](int cix, int s) {
        const int k0 = cix * KC;
        const uint32_t uAh = usm + s * STAGE;
        const uint32_t uAl = uAh + A_TILE;
        const __nv_bfloat16* srcH = g_hHi + (size_t)(m0 + ar) * HCW + k0;
        const __nv_bfloat16* srcL = g_hLo + (size_t)(m0 + ar) * HCW + k0;
#pragma unroll
        for (int h = 0; h < 2; h++) {
            int j = ajj + h;
            uint32_t off = (uint32_t)ar * 128 + ((j ^ (ar & 7)) << 4);
            cp16(uAh + off, srcH + j * 8);
            cp16(uAl + off, srcL + j * 8);
        }
    };
    auto cpB = [&](int cix, int s) {
        const int k0 = cix * KC;
        const uint32_t uBh = usm + s * STAGE + 2 * A_TILE;
        const uint32_t uBl = uBh + B_TILE;
        int j = tid & 7;
#pragma unroll
        for (int pass = 0; pass < 4; pass++) {
            int n = pass * 32 + (tid >> 3);
            size_t goff = (size_t)(n0 + n) * HCW + k0 + j * 8;
            uint32_t off = (uint32_t)n * 128 + ((j ^ (n & 7)) << 4);
            cp16(uBh + off, g_Bhi + goff);
            cp16(uBl + off, g_Blo + goff);
        }
    };

    float c[2][4][4];
#pragma unroll
    for (int i = 0; i < 2; i++)
#pragma unroll
        for (int j = 0; j < 4; j++)
#pragma unroll
            for (int q = 0; q < 4; q++) c[i][j][q] = 0.0f;

    const int lsub = lane >> 3, lrr = lane & 7;

    cpA(0, 0); cpB(0, 0); CP_COMMIT();

    for (int cix = 0; cix < nChunks; cix++) {
        const int cur = cix & 1, nxt = cur ^ 1;
        CP_WAIT0();
        __syncthreads();
        if (cix + 1 < nChunks) { cpA(cix + 1, nxt); cpB(cix + 1, nxt); CP_COMMIT(); }

        const uint32_t uAh = usm + cur * STAGE;
        const uint32_t uAl = uAh + A_TILE;
        const uint32_t uBh = uAh + 2 * A_TILE;
        const uint32_t uBl = uBh + B_TILE;

#pragma unroll
        for (int ks = 0; ks < 4; ks++) {
            uint32_t a_hi[2][4], a_lo[2][4];
            int kb = ks * 2 + (lsub >> 1);
#pragma unroll
            for (int mf = 0; mf < 2; mf++) {
                int row = wm * 32 + mf * 16 + (lsub & 1) * 8 + lrr;
                uint32_t addr = (uint32_t)row * 128 + ((kb ^ (row & 7)) << 4);
                ldsm4(a_hi[mf], uAh + addr);
                ldsm4(a_lo[mf], uAl + addr);
            }
#pragma unroll
            for (int gi = 0; gi < 2; gi++) {
                int n  = wn * 32 + (gi * 2 + (lsub & 1)) * 8 + lrr;
                uint32_t addr = (uint32_t)n * 128 + ((kb ^ (n & 7)) << 4);
                uint32_t bh[4], bl[4];
                ldsm4(bh, uBh + addr);
                ldsm4(bl, uBl + addr);
#pragma unroll
                for (int mf = 0; mf < 2; mf++) {
                    mma16816(c[mf][2*gi],     a_hi[mf], bh[0], bh[2]);
                    mma16816(c[mf][2*gi + 1], a_hi[mf], bh[1], bh[3]);
                    mma16816(c[mf][2*gi],     a_hi[mf], bl[0], bl[2]);
                    mma16816(c[mf][2*gi + 1], a_hi[mf], bl[1], bl[3]);
                    mma16816(c[mf][2*gi],     a_lo[mf], bh[0], bh[2]);
                    mma16816(c[mf][2*gi + 1], a_lo[mf], bh[1], bh[3]);
                }
            }
        }
    }

    const int qr = lane >> 2;
    const int qc = (lane & 3) * 2;
#pragma unroll
    for (int mf = 0; mf < 2; mf++) {
#pragma unroll
        for (int half = 0; half < 2; half++) {
            int row = m0 + wm * 32 + mf * 16 + half * 8 + qr;
            if (row < M) {
#pragma unroll
                for (int nf = 0; nf < 4; nf++) {
                    int col = n0 + wn * 32 + nf * 8 + qc;
                    float2 v = make_float2(c[mf][nf][2*half], c[mf][nf][2*half + 1]);
                    *(float2*)(g_AB + (size_t)row * ABW + col) = v;
                }
            }
        }
    }
}

// ============================================================================
// edge gemm: 64 edges x FULL N=256 in ONE pass (gather once), KC=32,
// 512 threads (16 warps, 2m x 8n, 32x32 warp tiles), double-buffered A+B,
// 1 CTA/SM. ldA(c+1) hoisted above the wait/sync for latency cover.
// Epilogue: C (64x256) stashed in stage smem, sorted-dst column scan, atomics.
// ============================================================================
__global__ __launch_bounds__(512, 1)
void edge_gemm(const float* __restrict__ b1, const float* __restrict__ b2) {
    extern __shared__ __align__(128) char dsm[];
    char* sbase = (char*)(((uintptr_t)dsm + 127) & ~(uintptr_t)127);
    const uint32_t usm = smem_u32(sbase);

    __shared__ int   sSrc[64];
    __shared__ int   sDst[64];
    __shared__ __align__(16) float sB1[256];
    __shared__ float sB2[256];

    const int tid  = threadIdx.x;
    const int wid  = tid >> 5, lane = tid & 31;
    const int wm   = wid & 1;            // m group of 32
    const int wn   = wid >> 1;           // n group of 32 (0..7)
    const int m0   = blockIdx.x * 64;
    const int lsub = lane >> 3, lrr = lane & 7;

    if (tid < 64) {
        sSrc[tid] = g_srt_src[m0 + tid];
        sDst[tid] = g_srt_dst[m0 + tid];
    }
    if (tid < 256) { sB1[tid] = b1[tid]; sB2[tid] = b2[tid]; }
    __syncthreads();

    // gather assignment: 8 threads per row, 4 floats each
    const int ar  = tid >> 3;            // row 0..63
    const int tq8 = tid & 7;             // k-eighth (4 floats)
    const int adn = sDst[ar];
    const int asn = sSrc[ar];

    float4 zr0, zr1;
    auto ldA = [&](int c) {
        const int k0 = c * EKC + tq8 * 4;
        zr0 = *(const float4*)(g_AB + (size_t)adn * ABW + k0);
        zr1 = *(const float4*)(g_AB + (size_t)asn * ABW + 256 + k0);
    };
    auto stA = [&](int c, int s) {
        const int k0 = c * EKC + tq8 * 4;
        float z0 = fmaxf(zr0.x + zr1.x + sB1[k0 + 0], 0.0f);
        float z1 = fmaxf(zr0.y + zr1.y + sB1[k0 + 1], 0.0f);
        float z2 = fmaxf(zr0.z + zr1.z + sB1[k0 + 2], 0.0f);
        float z3 = fmaxf(zr0.w + zr1.w + sB1[k0 + 3], 0.0f);
        uint32_t h0, l0, h1, l1;
        split2(z0, z1, h0, l0);
        split2(z2, z3, h1, l1);
        int kb16 = tq8 >> 1;                 // 16B chunk index 0..3
        uint32_t off = (uint32_t)ar * 64 + ((kb16 ^ ((ar >> 1) & 3)) << 4)
                     + (uint32_t)(tq8 & 1) * 8;
        char* pAhi = sbase + s * ESTAGE2;
        char* pAlo = pAhi + EA2_TILE;
        *(uint2*)(pAhi + off) = make_uint2(h0, h1);
        *(uint2*)(pAlo + off) = make_uint2(l0, l1);
    };
    // B tile: 256 n x 32 k (64B rows), swizzle kb ^ ((n>>1)&3)
    const int bn = tid >> 1, bh2 = tid & 1;
    auto cpB = [&](int c, int s) {
        const uint32_t uBh = usm + s * ESTAGE2 + 2 * EA2_TILE;
        const uint32_t uBl = uBh + EB2_TILE;
        size_t gbase = (size_t)bn * FDIM + c * EKC;
#pragma unroll
        for (int h = 0; h < 2; h++) {
            int kb = 2 * bh2 + h;
            uint32_t off = (uint32_t)bn * 64 + ((kb ^ ((bn >> 1) & 3)) << 4);
            cp16(uBh + off, g_Bhi + gbase + kb * 8);
            cp16(uBl + off, g_Blo + gbase + kb * 8);
        }
        CP_COMMIT();
    };

    float c[2][4][4];
#pragma unroll
    for (int i = 0; i < 2; i++)
#pragma unroll
        for (int j = 0; j < 4; j++)
#pragma unroll
            for (int q = 0; q < 4; q++) c[i][j][q] = 0.0f;

    // prologue
    ldA(0);
    cpB(0, 0);
    stA(0, 0);

    for (int cc = 0; cc < 8; cc++) {
        const int cur = cc & 1, nxt = cur ^ 1;
        const bool more = (cc + 1 < 8);
        if (more) ldA(cc + 1);     // LDGs in flight over wait+sync+mma
        CP_WAIT0();                // B(cc) resident
        __syncthreads();           // A(cc) visible; stage nxt free
        if (more) cpB(cc + 1, nxt);

        const uint32_t aCh = usm + cur * ESTAGE2;
        const uint32_t aCl = aCh + EA2_TILE;
        const uint32_t uBh = aCh + 2 * EA2_TILE;
        const uint32_t uBl = uBh + EB2_TILE;

#pragma unroll
        for (int ks = 0; ks < 2; ks++) {
            uint32_t a_hi[2][4], a_lo[2][4];
            int kb = ks * 2 + (lsub >> 1);
#pragma unroll
            for (int mf = 0; mf < 2; mf++) {
                int row = wm * 32 + mf * 16 + (lsub & 1) * 8 + lrr;
                uint32_t addr = (uint32_t)row * 64 + ((kb ^ ((row >> 1) & 3)) << 4);
                ldsm4(a_hi[mf], aCh + addr);
                ldsm4(a_lo[mf], aCl + addr);
            }
#pragma unroll
            for (int gi = 0; gi < 2; gi++) {
                int n = wn * 32 + (gi * 2 + (lsub & 1)) * 8 + lrr;
                uint32_t addr = (uint32_t)n * 64 + ((kb ^ ((n >> 1) & 3)) << 4);
                uint32_t bh[4], bl[4];
                ldsm4(bh, uBh + addr);
                ldsm4(bl, uBl + addr);
#pragma unroll
                for (int mf = 0; mf < 2; mf++) {
                    mma16816(c[mf][2*gi],     a_hi[mf], bh[0], bh[2]);
                    mma16816(c[mf][2*gi + 1], a_hi[mf], bh[1], bh[3]);
                    mma16816(c[mf][2*gi],     a_hi[mf], bl[0], bl[2]);
                    mma16816(c[mf][2*gi + 1], a_hi[mf], bl[1], bl[3]);
                    mma16816(c[mf][2*gi],     a_lo[mf], bh[0], bh[2]);
                    mma16816(c[mf][2*gi + 1], a_lo[mf], bh[1], bh[3]);
                }
            }
        }

        if (more) stA(cc + 1, nxt);
    }

    // ---- epilogue: stash C (64x256 fp32 = 64KB) over the stage smem,
    //      per-column segment-max scan over sorted dst, few atomics ----
    __syncthreads();                       // all mma (all warps) done
    float* sC = (float*)sbase;
    const int qr = lane >> 2, qc = (lane & 3) * 2;
#pragma unroll
    for (int mf = 0; mf < 2; mf++) {
#pragma unroll
        for (int half = 0; half < 2; half++) {
            int row = wm * 32 + mf * 16 + half * 8 + qr;
#pragma unroll
            for (int nf = 0; nf < 4; nf++) {
                int col = wn * 32 + nf * 8 + qc;
                sC[row * 256 + col]     = c[mf][nf][2*half];
                sC[row * 256 + col + 1] = c[mf][nf][2*half + 1];
            }
        }
    }
    __syncthreads();
    if (tid < 256) {
        const int col = tid;
        const float bb = sB2[col];
        float run = sC[col];
        int prev = sDst[0];
        for (int r = 1; r < 64; r++) {
            int d = sDst[r];
            float v = sC[r * 256 + col];
            if (d != prev) {
                atomicMaxF(&g_seg[(size_t)prev * FDIM + col], run + bb);
                run = v; prev = d;
            } else {
                run = fmaxf(run, v);
            }
        }
        atomicMaxF(&g_seg[(size_t)prev * FDIM + col], run + bb);
    }
}

// ============================================================================
// layer-3 edge kernel (W2 is 256x3): one warp per edge
// ============================================================================
__global__ void edge3_kernel(const float* __restrict__ b1,
                             const float* __restrict__ W3, const float* __restrict__ b2) {
    __shared__ float sW[768];
    __shared__ float sB1[256];
    int tid = threadIdx.x;
    for (int i = tid; i < 768; i += 256) sW[i] = W3[i];
    sB1[tid] = b1[tid];
    __syncthreads();
    int warp = tid >> 5, lane = tid & 31;
    int e = blockIdx.x * 8 + warp;
    int s = g_srt_src[e], d = g_srt_dst[e];
    const float* Ad = &g_AB[(size_t)d * ABW];
    const float* Bs = &g_AB[(size_t)s * ABW + 256];
    float s0 = 0.f, s1 = 0.f, s2 = 0.f;
#pragma unroll
    for (int k = lane; k < 256; k += 32) {
        float z = fmaxf(Ad[k] + Bs[k] + sB1[k], 0.0f);
        s0 = fmaf(z, sW[k * 3 + 0], s0);
        s1 = fmaf(z, sW[k * 3 + 1], s1);
        s2 = fmaf(z, sW[k * 3 + 2], s2);
    }
#pragma unroll
    for (int o = 16; o > 0; o >>= 1) {
        s0 += __shfl_down_sync(0xffffffff, s0, o);
        s1 += __shfl_down_sync(0xffffffff, s1, o);
        s2 += __shfl_down_sync(0xffffffff, s2, o);
    }
    if (lane == 0) {
        atomicMaxF(&g_seg[(size_t)d * 3 + 0], s0 + b2[0]);
        atomicMaxF(&g_seg[(size_t)d * 3 + 1], s1 + b2[1]);
        atomicMaxF(&g_seg[(size_t)d * 3 + 2], s2 + b2[2]);
    }
}

// fin12: hcat cols [0,256) = relu(seg) as bf16 hi/lo
__global__ void fin12_kernel() {
    int i = blockIdx.x, j = threadIdx.x;
    float v = g_seg[(size_t)i * FDIM + j];
    v = (v > 0.0f) ? v : 0.0f;
    __nv_bfloat16 hi, lo; split1(v, hi, lo);
    g_hHi[(size_t)i * HCW + j] = hi;
    g_hLo[(size_t)i * HCW + j] = lo;
}

__global__ void fin3_kernel(const float* __restrict__ t, float* __restrict__ out) {
    int idx = blockIdx.x * 256 + threadIdx.x;
    if (idx >= N_NODES * 3) return;
    int i = idx / 3;
    const float ln_sigma = 3.2188758248682006f;   // ln 25
    float tt = t[i];
    float sd = sqrtf((expf(2.0f * tt * ln_sigma) - 1.0f) / (2.0f * ln_sigma));
    float v = g_seg[idx];
    if (!isfinite(v)) v = 0.0f;
    out[idx] = v / (sd + 1e-7f);
}

// ============================================================================
extern "C" void kernel_launch(void* const* d_in, const int* in_sizes, int n_in,
                              void* d_out, int out_size) {
    const float* x    = (const float*)d_in[0];
    const int*   eidx = (const int*)d_in[1];    // int32 (JAX x64 disabled)
    const float* t    = (const float*)d_in[2];
    const float* emb  = (const float*)d_in[3];
    const float* encW = (const float*)d_in[4];
    const float* encb = (const float*)d_in[5];
    const float* fw   = (const float*)d_in[6];
    const float* teW  = (const float*)d_in[7];
    const float* teb  = (const float*)d_in[8];
    const float* W1[3] = {(const float*)d_in[9],  (const float*)d_in[13], (const float*)d_in[17]};
    const float* b1[3] = {(const float*)d_in[10], (const float*)d_in[14], (const float*)d_in[18]};
    const float* W2[3] = {(const float*)d_in[11], (const float*)d_in[15], (const float*)d_in[19]};
    const float* b2[3] = {(const float*)d_in[12], (const float*)d_in[16], (const float*)d_in[20]};
    float* out = (float*)d_out;
    (void)in_sizes; (void)n_in; (void)out_size;

    cudaFuncSetAttribute(node_gemm, cudaFuncAttributeMaxDynamicSharedMemorySize, DSMEM);
    cudaFuncSetAttribute(edge_gemm, cudaFuncAttributeMaxDynamicSharedMemorySize, DSMEM_EDGE);

    // edge sort (once per launch)
    zero_cnt_kernel<<<(N_NODES + 255) / 256, 256>>>();
    hist_kernel<<<N_EDGES / 256, 256>>>(eidx);
    scan_kernel<<<1, 1024>>>();
    scatter_kernel<<<N_EDGES / 256, 256>>>(eidx);

    temb_kernel<<<N_NODES / 8, 256>>>(t, fw, teW, teb);
    enc_kernel<<<N_NODES, 256>>>(x, encW, encb, emb);

    dim3 gNode((N_NODES + BM - 1) / BM, ABW / BN);   // 157 x 4

    for (int l = 0; l < 3; l++) {
        prepWc_kernel<<<(512 * 768) / 256, 256>>>(W1[l]);
        node_gemm<<<gNode, 256, DSMEM>>>(N_NODES);
        if (l < 2) {
            prepW2_kernel<<<(256 * 256) / 256, 256>>>(W2[l]);
            init_kernel<<<(N_NODES * FDIM) / 256, 256>>>(N_NODES * FDIM);
            edge_gemm<<<N_EDGES / 64, 512, DSMEM_EDGE>>>(b1[l], b2[l]);
            fin12_kernel<<<N_NODES, 256>>>();
        } else {
            init_kernel<<<(N_NODES * 3 + 255) / 256, 256>>>(N_NODES * 3);
            edge3_kernel<<<N_EDGES / 8, 256>>>(b1[l], W2[l], b2[l]);
            fin3_kernel<<<(N_NODES * 3 + 255) / 256, 256>>>(t, out);
        }
    }
}

// round 16
// speedup vs baseline: 1.1429x; 1.1429x over previous
#include <cuda_runtime.h>
#include <cuda_bf16.h>
#include <math.h>
#include <stdint.h>

#define N_NODES 10000
#define N_EDGES 160000
#define FDIM    256
#define HCW     768   // hcat: [h(256) | temb(256) | emb_pcs(256)]
#define ABW     512   // [A(256) | B(256)] per node

// node/edge gemm tiling: 64(M) x 128(N), KC=64, 8 warps (2m x 4n)
#define BM   64
#define BN   128
#define KC   64
#define A_TILE (BM * KC * 2)
#define B_TILE (BN * KC * 2)
#define STAGE  (2 * A_TILE + 2 * B_TILE)       // 49152 B
#define DSMEM  (2 * STAGE + 128)               // ~96KB -> 2 CTA/SM

// -------- device scratch ----------------------------------------------------
__device__ __align__(16) float g_AB  [N_NODES * ABW];
__device__ __align__(16) float g_seg [N_NODES * FDIM];
__device__ __align__(16) __nv_bfloat16 g_hHi[(N_NODES + 64) * HCW];
__device__ __align__(16) __nv_bfloat16 g_hLo[(N_NODES + 64) * HCW];
__device__ __align__(16) __nv_bfloat16 g_Bhi[512 * 768];   // W^T hi [n][k]
__device__ __align__(16) __nv_bfloat16 g_Blo[512 * 768];   // W^T lo [n][k]
// edge sort
__device__ int g_cnt[N_NODES];
__device__ int g_cur[N_NODES];
__device__ int g_srt_src[N_EDGES];
__device__ int g_srt_dst[N_EDGES];

// -------- helpers -----------------------------------------------------------
__device__ __forceinline__ void atomicMaxF(float* addr, float v) {
    if (v >= 0.0f) atomicMax((int*)addr, __float_as_int(v));
    else           atomicMin((unsigned int*)addr, __float_as_uint(v));
}
__device__ __forceinline__ uint32_t smem_u32(const void* p) {
    uint32_t a;
    asm("{ .reg .u64 t; cvta.to.shared.u64 t, %1; cvt.u32.u64 %0, t; }" : "=r"(a) : "l"(p));
    return a;
}
__device__ __forceinline__ void ldsm4(uint32_t* r, uint32_t addr) {
    asm volatile("ldmatrix.sync.aligned.m8n8.x4.shared.b16 {%0,%1,%2,%3}, [%4];"
                 : "=r"(r[0]), "=r"(r[1]), "=r"(r[2]), "=r"(r[3]) : "r"(addr));
}
__device__ __forceinline__ void mma16816(float* c, const uint32_t* a,
                                         uint32_t b0, uint32_t b1) {
    asm volatile("mma.sync.aligned.m16n8k16.row.col.f32.bf16.bf16.f32 "
                 "{%0,%1,%2,%3}, {%4,%5,%6,%7}, {%8,%9}, {%0,%1,%2,%3};"
                 : "+f"(c[0]), "+f"(c[1]), "+f"(c[2]), "+f"(c[3])
                 : "r"(a[0]), "r"(a[1]), "r"(a[2]), "r"(a[3]), "r"(b0), "r"(b1));
}
__device__ __forceinline__ void cp16(uint32_t daddr, const void* gptr) {
    asm volatile("cp.async.cg.shared.global [%0], [%1], 16;"
                 :: "r"(daddr), "l"(gptr) : "memory");
}
#define CP_COMMIT() asm volatile("cp.async.commit_group;" ::: "memory")
#define CP_WAIT0()  asm volatile("cp.async.wait_group 0;" ::: "memory")

__device__ __forceinline__ void split2(float z0, float z1, uint32_t& hi, uint32_t& lo) {
    __nv_bfloat16 h0 = __float2bfloat16(z0), h1 = __float2bfloat16(z1);
    __nv_bfloat16 l0 = __float2bfloat16(z0 - __bfloat162float(h0));
    __nv_bfloat16 l1 = __float2bfloat16(z1 - __bfloat162float(h1));
    hi = (uint32_t)__bfloat16_as_ushort(h0) | ((uint32_t)__bfloat16_as_ushort(h1) << 16);
    lo = (uint32_t)__bfloat16_as_ushort(l0) | ((uint32_t)__bfloat16_as_ushort(l1) << 16);
}
__device__ __forceinline__ void split1(float v, __nv_bfloat16& hi, __nv_bfloat16& lo) {
    hi = __float2bfloat16(v);
    lo = __float2bfloat16(v - __bfloat162float(hi));
}

// ============================================================================
// edge sort: counting sort by dst (order within dst nondeterministic — OK,
// max is order-independent, exact in fp32)
// ============================================================================
__global__ void zero_cnt_kernel() {
    int i = blockIdx.x * 256 + threadIdx.x;
    if (i < N_NODES) g_cnt[i] = 0;
}
__global__ void hist_kernel(const int* __restrict__ eidx) {
    int e = blockIdx.x * 256 + threadIdx.x;
    atomicAdd(&g_cnt[eidx[N_EDGES + e]], 1);
}
__global__ void scan_kernel() {     // 1 block, 1024 threads, 10 elems/thread
    __shared__ int sTot[1024];
    int tx = threadIdx.x;
    int base = tx * 10;
    int local[10];
    int s = 0;
    if (tx < 1000) {
#pragma unroll
        for (int j = 0; j < 10; j++) { local[j] = s; s += g_cnt[base + j]; }
    }
    sTot[tx] = (tx < 1000) ? s : 0;
    __syncthreads();
    for (int off = 1; off < 1024; off <<= 1) {
        int add = (tx >= off) ? sTot[tx - off] : 0;
        __syncthreads();
        sTot[tx] += add;
        __syncthreads();
    }
    if (tx < 1000) {
        int pre = (tx == 0) ? 0 : sTot[tx - 1];
#pragma unroll
        for (int j = 0; j < 10; j++) g_cur[base + j] = pre + local[j];
    }
}
__global__ void scatter_kernel(const int* __restrict__ eidx) {
    int e = blockIdx.x * 256 + threadIdx.x;
    int d = eidx[N_EDGES + e];
    int pos = atomicAdd(&g_cur[d], 1);
    g_srt_dst[pos] = d;
    g_srt_src[pos] = eidx[e];
}

// ============================================================================
// small kernels — temb/enc/fin12 write PRE-SPLIT bf16 hi/lo hcat
// ============================================================================
__global__ void temb_kernel(const float* __restrict__ t, const float* __restrict__ fw,
                            const float* __restrict__ teW, const float* __restrict__ teb) {
    __shared__ float v[8][256];
    int j = threadIdx.x, i0 = blockIdx.x * 8;
    if (j < 128) {
        float f = fw[j] * 6.283185307179586f;
#pragma unroll
        for (int r = 0; r < 8; r++) {
            float p = t[i0 + r] * f;
            v[r][j] = sinf(p); v[r][j + 128] = cosf(p);
        }
    }
    __syncthreads();
    float acc[8]; float bb = teb[j];
#pragma unroll
    for (int r = 0; r < 8; r++) acc[r] = bb;
    for (int k = 0; k < 256; k++) {
        float w = teW[k * 256 + j];
#pragma unroll
        for (int r = 0; r < 8; r++) acc[r] = fmaf(v[r][k], w, acc[r]);
    }
#pragma unroll
    for (int r = 0; r < 8; r++) {
        float a = acc[r];
        a = a / (1.0f + expf(-a));
        __nv_bfloat16 hi, lo; split1(a, hi, lo);
        size_t off = (size_t)(i0 + r) * HCW + 256 + j;
        g_hHi[off] = hi; g_hLo[off] = lo;
    }
}

__global__ void enc_kernel(const float* __restrict__ x, const float* __restrict__ encW,
                           const float* __restrict__ encb, const float* __restrict__ emb) {
    int i = blockIdx.x, j = threadIdx.x;
    float h = encb[j];
    h = fmaf(x[i * 3 + 0], encW[0 * 256 + j], h);
    h = fmaf(x[i * 3 + 1], encW[1 * 256 + j], h);
    h = fmaf(x[i * 3 + 2], encW[2 * 256 + j], h);
    __nv_bfloat16 hi, lo;
    split1(h, hi, lo);
    g_hHi[(size_t)i * HCW + j] = hi; g_hLo[(size_t)i * HCW + j] = lo;
    split1(emb[(size_t)i * 256 + j], hi, lo);
    g_hHi[(size_t)i * HCW + 512 + j] = hi; g_hLo[(size_t)i * HCW + 512 + j] = lo;
}

__global__ void prepWc_kernel(const float* __restrict__ W1) {
    int idx = blockIdx.x * 256 + threadIdx.x;     // 512*768
    int n = idx / 768, k = idx % 768;
    float v = (n < 256) ? (W1[k * 256 + n] - W1[(768 + k) * 256 + n])
                        : W1[(768 + k) * 256 + (n - 256)];
    __nv_bfloat16 hi, lo; split1(v, hi, lo);
    g_Bhi[idx] = hi; g_Blo[idx] = lo;
}

__global__ void prepW2_kernel(const float* __restrict__ W2) {
    int idx = blockIdx.x * 256 + threadIdx.x;     // 256*256
    int n = idx / 256, k = idx % 256;
    __nv_bfloat16 hi, lo; split1(W2[k * 256 + n], hi, lo);
    g_Bhi[idx] = hi; g_Blo[idx] = lo;
}

__global__ void init_kernel(int n) {
    int idx = blockIdx.x * 256 + threadIdx.x;
    if (idx < n) g_seg[idx] = __int_as_float(0xff800000);
}

// ============================================================================
// node gemm: g_AB[M,512] = hcat[M,768] @ Wc^T — all operands via cp.async
// (R10 version, measured 77us)
// ============================================================================
__global__ __launch_bounds__(256, 2)
void node_gemm(int M) {
    extern __shared__ __align__(128) char dsm[];
    char* sbase = (char*)(((uintptr_t)dsm + 127) & ~(uintptr_t)127);
    const uint32_t usm = smem_u32(sbase);

    const int tid  = threadIdx.x;
    const int wid  = tid >> 5, lane = tid & 31;
    const int wm   = wid & 1;
    const int wn   = wid >> 1;
    const int m0   = blockIdx.x * BM;
    const int n0   = blockIdx.y * BN;
    const int nChunks = HCW / KC;   // 12

    const int ar = tid >> 2, ajj = (tid & 3) * 2;
    auto cpA = [&](int cix, int s) {
        const int k0 = cix * KC;
        const uint32_t uAh = usm + s * STAGE;
        const uint32_t uAl = uAh + A_TILE;
        const __nv_bfloat16* srcH = g_hHi + (size_t)(m0 + ar) * HCW + k0;
        const __nv_bfloat16* srcL = g_hLo + (size_t)(m0 + ar) * HCW + k0;
#pragma unroll
        for (int h = 0; h < 2; h++) {
            int j = ajj + h;
            uint32_t off = (uint32_t)ar * 128 + ((j ^ (ar & 7)) << 4);
            cp16(uAh + off, srcH + j * 8);
            cp16(uAl + off, srcL + j * 8);
        }
    };
    auto cpB = [&](int cix, int s) {
        const int k0 = cix * KC;
        const uint32_t uBh = usm + s * STAGE + 2 * A_TILE;
        const uint32_t uBl = uBh + B_TILE;
        int j = tid & 7;
#pragma unroll
        for (int pass = 0; pass < 4; pass++) {
            int n = pass * 32 + (tid >> 3);
            size_t goff = (size_t)(n0 + n) * HCW + k0 + j * 8;
            uint32_t off = (uint32_t)n * 128 + ((j ^ (n & 7)) << 4);
            cp16(uBh + off, g_Bhi + goff);
            cp16(uBl + off, g_Blo + goff);
        }
    };

    float c[2][4][4];
#pragma unroll
    for (int i = 0; i < 2; i++)
#pragma unroll
        for (int j = 0; j < 4; j++)
#pragma unroll
            for (int q = 0; q < 4; q++) c[i][j][q] = 0.0f;

    const int lsub = lane >> 3, lrr = lane & 7;

    cpA(0, 0); cpB(0, 0); CP_COMMIT();

    for (int cix = 0; cix < nChunks; cix++) {
        const int cur = cix & 1, nxt = cur ^ 1;
        CP_WAIT0();
        __syncthreads();
        if (cix + 1 < nChunks) { cpA(cix + 1, nxt); cpB(cix + 1, nxt); CP_COMMIT(); }

        const uint32_t uAh = usm + cur * STAGE;
        const uint32_t uAl = uAh + A_TILE;
        const uint32_t uBh = uAh + 2 * A_TILE;
        const uint32_t uBl = uBh + B_TILE;

#pragma unroll
        for (int ks = 0; ks < 4; ks++) {
            uint32_t a_hi[2][4], a_lo[2][4];
            int kb = ks * 2 + (lsub >> 1);
#pragma unroll
            for (int mf = 0; mf < 2; mf++) {
                int row = wm * 32 + mf * 16 + (lsub & 1) * 8 + lrr;
                uint32_t addr = (uint32_t)row * 128 + ((kb ^ (row & 7)) << 4);
                ldsm4(a_hi[mf], uAh + addr);
                ldsm4(a_lo[mf], uAl + addr);
            }
#pragma unroll
            for (int gi = 0; gi < 2; gi++) {
                int n  = wn * 32 + (gi * 2 + (lsub & 1)) * 8 + lrr;
                uint32_t addr = (uint32_t)n * 128 + ((kb ^ (n & 7)) << 4);
                uint32_t bh[4], bl[4];
                ldsm4(bh, uBh + addr);
                ldsm4(bl, uBl + addr);
#pragma unroll
                for (int mf = 0; mf < 2; mf++) {
                    mma16816(c[mf][2*gi],     a_hi[mf], bh[0], bh[2]);
                    mma16816(c[mf][2*gi + 1], a_hi[mf], bh[1], bh[3]);
                    mma16816(c[mf][2*gi],     a_hi[mf], bl[0], bl[2]);
                    mma16816(c[mf][2*gi + 1], a_hi[mf], bl[1], bl[3]);
                    mma16816(c[mf][2*gi],     a_lo[mf], bh[0], bh[2]);
                    mma16816(c[mf][2*gi + 1], a_lo[mf], bh[1], bh[3]);
                }
            }
        }
    }

    const int qr = lane >> 2;
    const int qc = (lane & 3) * 2;
#pragma unroll
    for (int mf = 0; mf < 2; mf++) {
#pragma unroll
        for (int half = 0; half < 2; half++) {
            int row = m0 + wm * 32 + mf * 16 + half * 8 + qr;
            if (row < M) {
#pragma unroll
                for (int nf = 0; nf < 4; nf++) {
                    int col = n0 + wn * 32 + nf * 8 + qc;
                    float2 v = make_float2(c[mf][nf][2*half], c[mf][nf][2*half + 1]);
                    *(float2*)(g_AB + (size_t)row * ABW + col) = v;
                }
            }
        }
    }
}

// ============================================================================
// edge gemm (R10 shape + ldA hoist + parallel scan epilogue):
//   per chunk: ldA(c+1) [hoisted] -> wait B(c) -> sync -> cp.async B(c+1)
//              -> mma(c) -> split/store A(c+1)
//   epilogue: C tile -> smem; 256 threads = 2 row-halves x 128 cols,
//             sorted-dst segment-max scan, few atomics.
// ============================================================================
__global__ __launch_bounds__(256, 2)
void edge_gemm(const float* __restrict__ b1, const float* __restrict__ b2) {
    extern __shared__ __align__(128) char dsm[];
    char* sbase = (char*)(((uintptr_t)dsm + 127) & ~(uintptr_t)127);
    const uint32_t usm = smem_u32(sbase);

    __shared__ int   sSrc[BM];
    __shared__ int   sDst[BM];
    __shared__ __align__(16) float sB1[256];
    __shared__ float sB2[BN];

    const int tid  = threadIdx.x;
    const int wid  = tid >> 5, lane = tid & 31;
    const int wm   = wid & 1;
    const int wn   = wid >> 1;
    const int m0   = blockIdx.x * BM;
    const int n0   = blockIdx.y * BN;
    const int nChunks = FDIM / KC;   // 4

    if (tid < BM) {
        sSrc[tid] = g_srt_src[m0 + tid];
        sDst[tid] = g_srt_dst[m0 + tid];
    }
    sB1[tid] = b1[tid];
    if (tid < BN) sB2[tid] = b2[n0 + tid];
    __syncthreads();

    const int ar = tid >> 2;
    const int tq = tid & 3;
    const int adn = sDst[ar];
    const int asn = sSrc[ar];

    float zr0[16], zr1[16];

    auto ldA = [&](int cix) {
        const int k0 = cix * KC;
        const float4* pA = (const float4*)(g_AB + (size_t)adn * ABW + k0 + tq * 16);
        const float4* pB = (const float4*)(g_AB + (size_t)asn * ABW + 256 + k0 + tq * 16);
#pragma unroll
        for (int q = 0; q < 4; q++) {
            float4 a = pA[q], b = pB[q];
            zr0[4*q+0] = a.x; zr0[4*q+1] = a.y; zr0[4*q+2] = a.z; zr0[4*q+3] = a.w;
            zr1[4*q+0] = b.x; zr1[4*q+1] = b.y; zr1[4*q+2] = b.z; zr1[4*q+3] = b.w;
        }
    };
    auto stA = [&](int cix, int s) {
        char* pAhi = sbase + s * STAGE;
        char* pAlo = pAhi + A_TILE;
        const int k0 = cix * KC;
        float z[16];
#pragma unroll
        for (int q = 0; q < 16; q++)
            z[q] = fmaxf(zr0[q] + zr1[q] + sB1[k0 + tq * 16 + q], 0.0f);
#pragma unroll
        for (int half = 0; half < 2; half++) {
            uint32_t hi[4], lo[4];
#pragma unroll
            for (int e = 0; e < 4; e++)
                split2(z[8*half + 2*e], z[8*half + 2*e + 1], hi[e], lo[e]);
            int kb = tq * 2 + half;
            uint32_t off = (uint32_t)ar * 128 + ((kb ^ (ar & 7)) << 4);
            *(uint4*)(pAhi + off) = make_uint4(hi[0], hi[1], hi[2], hi[3]);
            *(uint4*)(pAlo + off) = make_uint4(lo[0], lo[1], lo[2], lo[3]);
        }
    };
    auto cpB = [&](int cix, int s) {
        const int k0 = cix * KC;
        const uint32_t uBh = usm + s * STAGE + 2 * A_TILE;
        const uint32_t uBl = uBh + B_TILE;
        int j = tid & 7;
#pragma unroll
        for (int pass = 0; pass < 4; pass++) {
            int n = pass * 32 + (tid >> 3);
            size_t goff = (size_t)(n0 + n) * FDIM + k0 + j * 8;
            uint32_t off = (uint32_t)n * 128 + ((j ^ (n & 7)) << 4);
            cp16(uBh + off, g_Bhi + goff);
            cp16(uBl + off, g_Blo + goff);
        }
        CP_COMMIT();
    };

    float c[2][4][4];
#pragma unroll
    for (int i = 0; i < 2; i++)
#pragma unroll
        for (int j = 0; j < 4; j++)
#pragma unroll
            for (int q = 0; q < 4; q++) c[i][j][q] = 0.0f;

    const int lsub = lane >> 3, lrr = lane & 7;

    ldA(0);
    cpB(0, 0);
    stA(0, 0);

    for (int cix = 0; cix < nChunks; cix++) {
        const int cur = cix & 1, nxt = cur ^ 1;
        const bool more = (cix + 1 < nChunks);
        if (more) ldA(cix + 1);   // HOIST: gather LDGs fly over wait+sync+mma
        CP_WAIT0();
        __syncthreads();
        if (more) cpB(cix + 1, nxt);

        const uint32_t uAh = usm + cur * STAGE;
        const uint32_t uAl = uAh + A_TILE;
        const uint32_t uBh = uAh + 2 * A_TILE;
        const uint32_t uBl = uBh + B_TILE;

#pragma unroll
        for (int ks = 0; ks < 4; ks++) {
            uint32_t a_hi[2][4], a_lo[2][4];
            int kb = ks * 2 + (lsub >> 1);
#pragma unroll
            for (int mf = 0; mf < 2; mf++) {
                int row = wm * 32 + mf * 16 + (lsub & 1) * 8 + lrr;
                uint32_t addr = (uint32_t)row * 128 + ((kb ^ (row & 7)) << 4);
                ldsm4(a_hi[mf], uAh + addr);
                ldsm4(a_lo[mf], uAl + addr);
            }
#pragma unroll
            for (int gi = 0; gi < 2; gi++) {
                int n  = wn * 32 + (gi * 2 + (lsub & 1)) * 8 + lrr;
                uint32_t addr = (uint32_t)n * 128 + ((kb ^ (n & 7)) << 4);
                uint32_t bh[4], bl[4];
                ldsm4(bh, uBh + addr);
                ldsm4(bl, uBl + addr);
#pragma unroll
                for (int mf = 0; mf < 2; mf++) {
                    mma16816(c[mf][2*gi],     a_hi[mf], bh[0], bh[2]);
                    mma16816(c[mf][2*gi + 1], a_hi[mf], bh[1], bh[3]);
                    mma16816(c[mf][2*gi],     a_hi[mf], bl[0], bl[2]);
                    mma16816(c[mf][2*gi + 1], a_hi[mf], bl[1], bl[3]);
                    mma16816(c[mf][2*gi],     a_lo[mf], bh[0], bh[2]);
                    mma16816(c[mf][2*gi + 1], a_lo[mf], bh[1], bh[3]);
                }
            }
        }

        if (more) stA(cix + 1, nxt);
    }

    // ---- epilogue: smem C tile; 256 threads = 2 row-halves x 128 cols;
    //      sorted-dst segment-max scan; boundary segments emit 1 extra atomic
    //      which max merges exactly ----
    __syncthreads();                       // all mma done; smem reusable
    float* sC = (float*)sbase;             // 64 x 128 fp32 = 32KB
    const int qr = lane >> 2, qc = (lane & 3) * 2;
#pragma unroll
    for (int mf = 0; mf < 2; mf++) {
#pragma unroll
        for (int half = 0; half < 2; half++) {
            int row = wm * 32 + mf * 16 + half * 8 + qr;
#pragma unroll
            for (int nf = 0; nf < 4; nf++) {
                int col = wn * 32 + nf * 8 + qc;
                sC[row * BN + col]     = c[mf][nf][2*half];
                sC[row * BN + col + 1] = c[mf][nf][2*half + 1];
            }
        }
    }
    __syncthreads();
    {
        const int col = tid & 127;
        const int r0  = (tid >> 7) * 32;       // rows [r0, r0+32)
        const float bb = sB2[col];
        float run = sC[r0 * BN + col];
        int prev = sDst[r0];
        for (int r = r0 + 1; r < r0 + 32; r++) {
            int d = sDst[r];
            float v = sC[r * BN + col];
            if (d != prev) {
                atomicMaxF(&g_seg[(size_t)prev * FDIM + n0 + col], run + bb);
                run = v; prev = d;
            } else {
                run = fmaxf(run, v);
            }
        }
        atomicMaxF(&g_seg[(size_t)prev * FDIM + n0 + col], run + bb);
    }
}

// ============================================================================
// layer-3 edge kernel (W2 is 256x3): one warp per edge
// ============================================================================
__global__ void edge3_kernel(const float* __restrict__ b1,
                             const float* __restrict__ W3, const float* __restrict__ b2) {
    __shared__ float sW[768];
    __shared__ float sB1[256];
    int tid = threadIdx.x;
    for (int i = tid; i < 768; i += 256) sW[i] = W3[i];
    sB1[tid] = b1[tid];
    __syncthreads();
    int warp = tid >> 5, lane = tid & 31;
    int e = blockIdx.x * 8 + warp;
    int s = g_srt_src[e], d = g_srt_dst[e];
    const float* Ad = &g_AB[(size_t)d * ABW];
    const float* Bs = &g_AB[(size_t)s * ABW + 256];
    float s0 = 0.f, s1 = 0.f, s2 = 0.f;
#pragma unroll
    for (int k = lane; k < 256; k += 32) {
        float z = fmaxf(Ad[k] + Bs[k] + sB1[k], 0.0f);
        s0 = fmaf(z, sW[k * 3 + 0], s0);
        s1 = fmaf(z, sW[k * 3 + 1], s1);
        s2 = fmaf(z, sW[k * 3 + 2], s2);
    }
#pragma unroll
    for (int o = 16; o > 0; o >>= 1) {
        s0 += __shfl_down_sync(0xffffffff, s0, o);
        s1 += __shfl_down_sync(0xffffffff, s1, o);
        s2 += __shfl_down_sync(0xffffffff, s2, o);
    }
    if (lane == 0) {
        atomicMaxF(&g_seg[(size_t)d * 3 + 0], s0 + b2[0]);
        atomicMaxF(&g_seg[(size_t)d * 3 + 1], s1 + b2[1]);
        atomicMaxF(&g_seg[(size_t)d * 3 + 2], s2 + b2[2]);
    }
}

// fin12: hcat cols [0,256) = relu(seg) as bf16 hi/lo
__global__ void fin12_kernel() {
    int i = blockIdx.x, j = threadIdx.x;
    float v = g_seg[(size_t)i * FDIM + j];
    v = (v > 0.0f) ? v : 0.0f;
    __nv_bfloat16 hi, lo; split1(v, hi, lo);
    g_hHi[(size_t)i * HCW + j] = hi;
    g_hLo[(size_t)i * HCW + j] = lo;
}

__global__ void fin3_kernel(const float* __restrict__ t, float* __restrict__ out) {
    int idx = blockIdx.x * 256 + threadIdx.x;
    if (idx >= N_NODES * 3) return;
    int i = idx / 3;
    const float ln_sigma = 3.2188758248682006f;   // ln 25
    float tt = t[i];
    float sd = sqrtf((expf(2.0f * tt * ln_sigma) - 1.0f) / (2.0f * ln_sigma));
    float v = g_seg[idx];
    if (!isfinite(v)) v = 0.0f;
    out[idx] = v / (sd + 1e-7f);
}

// ============================================================================
extern "C" void kernel_launch(void* const* d_in, const int* in_sizes, int n_in,
                              void* d_out, int out_size) {
    const float* x    = (const float*)d_in[0];
    const int*   eidx = (const int*)d_in[1];    // int32 (JAX x64 disabled)
    const float* t    = (const float*)d_in[2];
    const float* emb  = (const float*)d_in[3];
    const float* encW = (const float*)d_in[4];
    const float* encb = (const float*)d_in[5];
    const float* fw   = (const float*)d_in[6];
    const float* teW  = (const float*)d_in[7];
    const float* teb  = (const float*)d_in[8];
    const float* W1[3] = {(const float*)d_in[9],  (const float*)d_in[13], (const float*)d_in[17]};
    const float* b1[3] = {(const float*)d_in[10], (const float*)d_in[14], (const float*)d_in[18]};
    const float* W2[3] = {(const float*)d_in[11], (const float*)d_in[15], (const float*)d_in[19]};
    const float* b2[3] = {(const float*)d_in[12], (const float*)d_in[16], (const float*)d_in[20]};
    float* out = (float*)d_out;
    (void)in_sizes; (void)n_in; (void)out_size;

    cudaFuncSetAttribute(node_gemm, cudaFuncAttributeMaxDynamicSharedMemorySize, DSMEM);
    cudaFuncSetAttribute(edge_gemm, cudaFuncAttributeMaxDynamicSharedMemorySize, DSMEM);

    // edge sort (once per launch)
    zero_cnt_kernel<<<(N_NODES + 255) / 256, 256>>>();
    hist_kernel<<<N_EDGES / 256, 256>>>(eidx);
    scan_kernel<<<1, 1024>>>();
    scatter_kernel<<<N_EDGES / 256, 256>>>(eidx);

    temb_kernel<<<N_NODES / 8, 256>>>(t, fw, teW, teb);
    enc_kernel<<<N_NODES, 256>>>(x, encW, encb, emb);

    dim3 gNode((N_NODES + BM - 1) / BM, ABW / BN);   // 157 x 4
    dim3 gEdge(N_EDGES / BM, FDIM / BN);             // 2500 x 2

    for (int l = 0; l < 3; l++) {
        prepWc_kernel<<<(512 * 768) / 256, 256>>>(W1[l]);
        node_gemm<<<gNode, 256, DSMEM>>>(N_NODES);
        if (l < 2) {
            prepW2_kernel<<<(256 * 256) / 256, 256>>>(W2[l]);
            init_kernel<<<(N_NODES * FDIM) / 256, 256>>>(N_NODES * FDIM);
            edge_gemm<<<gEdge, 256, DSMEM>>>(b1[l], b2[l]);
            fin12_kernel<<<N_NODES, 256>>>();
        } else {
            init_kernel<<<(N_NODES * 3 + 255) / 256, 256>>>(N_NODES * 3);
            edge3_kernel<<<N_EDGES / 8, 256>>>(b1[l], W2[l], b2[l]);
            fin3_kernel<<<(N_NODES * 3 + 255) / 256, 256>>>(t, out);
        }
    }
}